// round 6
// baseline (speedup 1.0000x reference)
#include <cuda_runtime.h>
#include <cuda_bf16.h>

// ---------------- problem constants ----------------
#define Gn 4
#define Sn 2048
#define Dn 2048
#define En 64
#define NTOK (Gn*Sn)                  // 8192 tokens
#define NCOMB ((long long)NTOK*En*63) // 33,030,144 combine elements
#define MCTA 64
#define KC 64
#define NCHUNK (Dn/KC)                // 32
#define K1_THREADS 256
#define GEMM_BLOCKS (NTOK/MCTA)       // 128
#define K1_BLOCKS 148                 // 128 GEMM + 20 dedicated store CTAs
#define ZPC 8                         // zero-fill float4/thread/chunk (GEMM CTAs)
#define ZG ((long long)GEMM_BLOCKS*K1_THREADS*ZPC*NCHUNK)  // 8388608 float4

// ---------------- device scratch ----------------
__device__ float2 g_gate[NTOK];
__device__ int2   g_eidx[NTOK];
__device__ uchar2 g_lpos[NTOK];                 // block-local 0-indexed pos per slot
__device__ int    g_cnt[8*32*En];               // [gk][blk][expert] counts

// swizzled byte offset inside a 64x64-bf16 tile (128B rows, XOR-16B swizzle)
__device__ __forceinline__ unsigned swz(int row, int chunk) {
    return (unsigned)(row*128 + ((chunk ^ (row & 7)) << 4));
}

#define LDSM4(R0_,R1_,R2_,R3_,ADDR) \
  asm volatile("ldmatrix.sync.aligned.m8n8.x4.shared.b16 {%0,%1,%2,%3}, [%4];" \
    : "=r"(R0_),"=r"(R1_),"=r"(R2_),"=r"(R3_) : "r"(ADDR))
#define LDSM4T(R0_,R1_,R2_,R3_,ADDR) \
  asm volatile("ldmatrix.sync.aligned.m8n8.x4.trans.shared.b16 {%0,%1,%2,%3}, [%4];" \
    : "=r"(R0_),"=r"(R1_),"=r"(R2_),"=r"(R3_) : "r"(ADDR))
#define HMMA(C_,A0,A1,A2,A3,B0,B1) \
  asm volatile("mma.sync.aligned.m16n8k16.row.col.f32.bf16.bf16.f32 " \
    "{%0,%1,%2,%3}, {%4,%5,%6,%7}, {%8,%9}, {%0,%1,%2,%3};" \
    : "+f"(C_[0]),"+f"(C_[1]),"+f"(C_[2]),"+f"(C_[3]) \
    : "r"(A0),"r"(A1),"r"(A2),"r"(A3),"r"(B0),"r"(B1))

// ===== K1: zero-fill + bf16-split tensor GEMM + softmax/top2 + block-local scan =====
__global__ void __launch_bounds__(K1_THREADS)
k1_fused(const float* __restrict__ x, const float* __restrict__ W,
         const float* __restrict__ b, float* __restrict__ out, long long out_n)
{
    const int tid = threadIdx.x;
    const long long n4 = out_n >> 2;
    float4* o4 = (float4*)out;
    const float4 zz = make_float4(0.f, 0.f, 0.f, 0.f);

    // ---- dedicated store CTAs: drain second half of the zero-fill, then exit ----
    if (blockIdx.x >= GEMM_BLOCKS) {
        long long idx = (long long)(blockIdx.x - GEMM_BLOCKS)*K1_THREADS + tid;
        for (long long zi = ZG + idx; zi < n4; zi += (long long)(K1_BLOCKS - GEMM_BLOCKS)*K1_THREADS)
            o4[zi] = zz;
        return;
    }

    __shared__ __align__(16) unsigned char sm[32768];
    const unsigned sb = (unsigned)__cvta_generic_to_shared(sm);
    const unsigned XH = 0, XL = 8192, WHs = 16384, WLs = 24576;

    const int T0   = blockIdx.x * MCTA;
    const int lane = tid & 31, w = tid >> 5;
    const int R0 = (w & 3) * 16;     // 16 token rows per warp
    const int C0 = (w >> 2) * 32;    // 32 experts per warp

    const long long zbase = (long long)blockIdx.x*K1_THREADS + tid;
    const long long zstr  = (long long)GEMM_BLOCKS*K1_THREADS;
    if (blockIdx.x == 0 && tid < (int)(out_n & 3LL)) out[n4*4 + tid] = 0.f;

    float acc[4][4];
#pragma unroll
    for (int i = 0; i < 4; ++i)
#pragma unroll
        for (int j = 0; j < 4; ++j) acc[i][j] = 0.f;

    // prefetch chunk 0
    float2 xv[8], wv[8];
#pragma unroll
    for (int i = 0; i < 8; ++i) {
        int idx = tid + K1_THREADS*i;
        int row = idx >> 5, p = idx & 31;
        xv[i] = *(const float2*)(x + (size_t)(T0 + row)*Dn + 2*p);
        wv[i] = *(const float2*)(W + (size_t)row*En + 2*p);
    }

    const int lm = lane >> 3;
    const int lr = lane & 7;
    const int arow = R0 + ((lm & 1) << 3) + lr;
    const int half = lm >> 1;

    for (int c = 0; c < NCHUNK; ++c) {
        __syncthreads();                      // tiles free
#pragma unroll
        for (int i = 0; i < 8; ++i) {
            int idx = tid + K1_THREADS*i;
            int row = idx >> 5, p = idx & 31;
            unsigned off = swz(row, p >> 2) + ((p & 3) << 2);
            __nv_bfloat162 h, l;
            h.x = __float2bfloat16(xv[i].x);
            h.y = __float2bfloat16(xv[i].y);
            l.x = __float2bfloat16(xv[i].x - __bfloat162float(h.x));
            l.y = __float2bfloat16(xv[i].y - __bfloat162float(h.y));
            *(__nv_bfloat162*)(sm + XH + off) = h;
            *(__nv_bfloat162*)(sm + XL + off) = l;
            h.x = __float2bfloat16(wv[i].x);
            h.y = __float2bfloat16(wv[i].y);
            l.x = __float2bfloat16(wv[i].x - __bfloat162float(h.x));
            l.y = __float2bfloat16(wv[i].y - __bfloat162float(h.y));
            *(__nv_bfloat162*)(sm + WHs + off) = h;
            *(__nv_bfloat162*)(sm + WLs + off) = l;
        }
        if (c + 1 < NCHUNK) {
            const int dc0 = (c + 1)*KC;
#pragma unroll
            for (int i = 0; i < 8; ++i) {
                int idx = tid + K1_THREADS*i;
                int row = idx >> 5, p = idx & 31;
                xv[i] = *(const float2*)(x + (size_t)(T0 + row)*Dn + dc0 + 2*p);
                wv[i] = *(const float2*)(W + (size_t)(dc0 + row)*En + 2*p);
            }
        }
        // interleaved zero-fill batch (first half of output region)
#pragma unroll
        for (int j = 0; j < ZPC; ++j) {
            long long zi = zbase + (long long)(c*ZPC + j)*zstr;
            if (zi < n4) o4[zi] = zz;
        }
        __syncthreads();                      // tiles ready

#pragma unroll
        for (int ks = 0; ks < 4; ++ks) {
            unsigned ah0,ah1,ah2,ah3, al0,al1,al2,al3;
            const unsigned aoff = swz(arow, 2*ks + half);
            LDSM4(ah0,ah1,ah2,ah3, sb + XH + aoff);
            LDSM4(al0,al1,al2,al3, sb + XL + aoff);
            const int krow = 16*ks + ((lm & 1) << 3) + lr;
            unsigned bh[8], bl[8];
            const unsigned boff0 = swz(krow, (C0 >> 3) + half);
            const unsigned boff1 = swz(krow, (C0 >> 3) + 2 + half);
            LDSM4T(bh[0],bh[1],bh[2],bh[3], sb + WHs + boff0);
            LDSM4T(bh[4],bh[5],bh[6],bh[7], sb + WHs + boff1);
            LDSM4T(bl[0],bl[1],bl[2],bl[3], sb + WLs + boff0);
            LDSM4T(bl[4],bl[5],bl[6],bl[7], sb + WLs + boff1);
#pragma unroll
            for (int nt = 0; nt < 4; ++nt) {
                HMMA(acc[nt], ah0,ah1,ah2,ah3, bh[2*nt], bh[2*nt+1]);
                HMMA(acc[nt], ah0,ah1,ah2,ah3, bl[2*nt], bl[2*nt+1]);
                HMMA(acc[nt], al0,al1,al2,al3, bh[2*nt], bh[2*nt+1]);
            }
        }
    }

    // ---- epilogue: accs -> smem logits -> softmax + top2 per token ----
    __syncthreads();                          // reuse sm
    float* lg = (float*)sm;                   // [64][64] at sm+0 (16 KB)
    unsigned char* se   = sm + 16384;         // [2][64] expert idx per slot
    unsigned char* lpos = sm + 16544;         // [2][64] local position
    int*           cntl = (int*)(sm + 16768); // [2][64] per-expert counts
    {
        const int g = lane >> 2, cc = (lane & 3)*2;
#pragma unroll
        for (int nt = 0; nt < 4; ++nt) {
            int e = C0 + nt*8 + cc;
            lg[(R0 + g)*En + e]     = acc[nt][0];
            lg[(R0 + g)*En + e + 1] = acc[nt][1];
            lg[(R0 + g + 8)*En + e]     = acc[nt][2];
            lg[(R0 + g + 8)*En + e + 1] = acc[nt][3];
        }
    }
    __syncthreads();

    {
        float2 bb = ((const float2*)b)[lane];
        const int e0 = 2*lane, e1 = 2*lane + 1;
        for (int r = w*8; r < w*8 + 8; ++r) {
            float2 v = *(float2*)&lg[r*En + 2*lane];
            float l0 = v.x + bb.x, l1 = v.y + bb.y;

            float m = fmaxf(l0, l1);
#pragma unroll
            for (int o = 16; o > 0; o >>= 1) m = fmaxf(m, __shfl_xor_sync(0xffffffffu, m, o));
            float p0 = expf(l0 - m), p1 = expf(l1 - m);
            float s = p0 + p1;
#pragma unroll
            for (int o = 16; o > 0; o >>= 1) s += __shfl_xor_sync(0xffffffffu, s, o);
            p0 = p0 / s;
            p1 = p1 / s;

            float wp; int we;
            if (p1 > p0) { wp = p1; we = e1; } else { wp = p0; we = e0; }
#pragma unroll
            for (int o = 16; o > 0; o >>= 1) {
                float op = __shfl_xor_sync(0xffffffffu, wp, o);
                int   oe = __shfl_xor_sync(0xffffffffu, we, o);
                if (op > wp || (op == wp && oe < we)) { wp = op; we = oe; }
            }
            float a0 = (e0 == we) ? -1.f : p0;
            float a1 = (e1 == we) ? -1.f : p1;
            float wp2; int we2;
            if (a1 > a0) { wp2 = a1; we2 = e1; } else { wp2 = a0; we2 = e0; }
#pragma unroll
            for (int o = 16; o > 0; o >>= 1) {
                float op = __shfl_xor_sync(0xffffffffu, wp2, o);
                int   oe = __shfl_xor_sync(0xffffffffu, we2, o);
                if (op > wp2 || (op == wp2 && oe < we2)) { wp2 = op; we2 = oe; }
            }
            if (lane == 0) {
                g_gate[T0 + r] = make_float2(wp, wp2);
                g_eidx[T0 + r] = make_int2(we, we2);
                se[r]      = (unsigned char)we;
                se[64 + r] = (unsigned char)we2;
            }
        }
    }
    __syncthreads();

    // ---- block-local rank scan for both slots (warps 0 and 1) ----
    if (tid < 128) cntl[tid] = 0;
    __syncthreads();
    if (w < 2) {
        const int slot = w;
#pragma unroll
        for (int it = 0; it < 2; ++it) {
            int t = it*32 + lane;
            int e = se[slot*64 + t];
            unsigned mask = __match_any_sync(0xffffffffu, e);
            int rank = __popc(mask & ((1u << lane) - 1u));
            int base = cntl[slot*64 + e];
            lpos[slot*64 + t] = (unsigned char)(base + rank);
            __syncwarp();
            if (rank == 0) cntl[slot*64 + e] = base + __popc(mask);
            __syncwarp();
        }
    }
    __syncthreads();

    const int gidx = T0 >> 11;              // group = T0 / Sn
    const int blk  = (T0 & (Sn - 1)) >> 6;  // 64-token block within group
    if (tid < 128) {
        int k = tid >> 6, e = tid & 63;
        g_cnt[((gidx*2 + k)*32 + blk)*En + e] = cntl[k*64 + e];
    }
    if (tid < 64)
        g_lpos[T0 + tid] = make_uchar2(lpos[tid], lpos[64 + tid]);
}

// ===== K3: 32 CTAs: per-expert prefix over blocks + scatter =====
__global__ void __launch_bounds__(256)
k3_scatter(float* __restrict__ out, long long out_n,
           const int* __restrict__ capp, int has_mask)
{
    __shared__ int base[8][En];

    const int gk = blockIdx.x >> 2, q = blockIdx.x & 3;
    const int g = gk >> 1, k = gk & 1;
    const int tid = threadIdx.x;
    int cap = 64;
    if (capp) { cap = capp[0]; if (cap > 64) cap = 64; }

    if (tid < En) {
        int acc = 0;
        const int e = tid;
        const int bend = q*8 + 8;
        for (int bq = 0; bq < bend; ++bq) {
            if (bq >= q*8) base[bq - q*8][e] = acc;
            acc += g_cnt[(gk*32 + bq)*En + e];
        }
    }
    __syncthreads();

#pragma unroll
    for (int it = 0; it < 2; ++it) {
        int sl = q*512 + it*256 + tid;          // position within group
        int t  = g*Sn + sl;
        int2   ei = g_eidx[t];
        float2 gg = g_gate[t];
        uchar2 lp = g_lpos[t];
        int   e    = k ? ei.y : ei.x;
        float gate = k ? gg.y : gg.x;
        int   pos0 = base[(sl >> 6) & 7][e] + (int)(k ? lp.y : lp.x);
        if (pos0 + 1 < cap) {
            long long off = ((long long)t*En + e)*63 + pos0;
            if (off < out_n) out[off] = gate;
            if (has_mask) {
                long long moff = NCOMB + off;
                if (moff < out_n) out[moff] = (gate != 0.f) ? 1.f : 0.f;
            }
        }
    }
}

// ================= launch =================
extern "C" void kernel_launch(void* const* d_in, const int* in_sizes, int n_in,
                              void* d_out, int out_size)
{
    const float* x = (const float*)d_in[0];
    const float* W = (const float*)d_in[1];
    const float* b = (const float*)d_in[2];
    const int* capp = (n_in >= 4) ? (const int*)d_in[3] : nullptr;
    float* out = (float*)d_out;
    long long out_n = (long long)out_size;
    int has_mask = (out_n >= 2LL*NCOMB) ? 1 : 0;

    k1_fused<<<K1_BLOCKS, K1_THREADS>>>(x, W, b, out, out_n);
    k3_scatter<<<32, 256>>>(out, out_n, capp, has_mask);
}

// round 7
// speedup vs baseline: 1.7296x; 1.7296x over previous
#include <cuda_runtime.h>
#include <cuda_bf16.h>

// ---------------- problem constants ----------------
#define Gn 4
#define Sn 2048
#define Dn 2048
#define En 64
#define NTOK (Gn*Sn)                  // 8192 tokens
#define NCOMB ((long long)NTOK*En*63) // 33,030,144 combine elements
#define MCTA 64
#define KC 64
#define NCHUNK (Dn/KC)                // 32
#define K1_THREADS 256
#define GEMM_BLOCKS (NTOK/MCTA)       // 128
#define K1_BLOCKS 148                 // 128 GEMM + 20 dedicated store CTAs
#define ZPC 12                        // zero-fill float4/thread/chunk (GEMM CTAs)
#define ZG ((long long)GEMM_BLOCKS*K1_THREADS*ZPC*NCHUNK)  // 12,582,912 float4

// ---------------- device scratch ----------------
__device__ float2 g_gate[NTOK];
__device__ int2   g_eidx[NTOK];
__device__ uchar2 g_lpos[NTOK];                 // block-local 0-indexed pos per slot
__device__ int    g_cnt[8*32*En];               // [gk][blk][expert] counts

// swizzled byte offset inside a 64x64-bf16 tile (128B rows, XOR-16B swizzle)
__device__ __forceinline__ unsigned swz(int row, int chunk) {
    return (unsigned)(row*128 + ((chunk ^ (row & 7)) << 4));
}

#define LDSM4(R0_,R1_,R2_,R3_,ADDR) \
  asm volatile("ldmatrix.sync.aligned.m8n8.x4.shared.b16 {%0,%1,%2,%3}, [%4];" \
    : "=r"(R0_),"=r"(R1_),"=r"(R2_),"=r"(R3_) : "r"(ADDR))
#define LDSM4T(R0_,R1_,R2_,R3_,ADDR) \
  asm volatile("ldmatrix.sync.aligned.m8n8.x4.trans.shared.b16 {%0,%1,%2,%3}, [%4];" \
    : "=r"(R0_),"=r"(R1_),"=r"(R2_),"=r"(R3_) : "r"(ADDR))
#define HMMA(C_,A0,A1,A2,A3,B0,B1) \
  asm volatile("mma.sync.aligned.m16n8k16.row.col.f32.bf16.bf16.f32 " \
    "{%0,%1,%2,%3}, {%4,%5,%6,%7}, {%8,%9}, {%0,%1,%2,%3};" \
    : "+f"(C_[0]),"+f"(C_[1]),"+f"(C_[2]),"+f"(C_[3]) \
    : "r"(A0),"r"(A1),"r"(A2),"r"(A3),"r"(B0),"r"(B1))

// ===== K1: zero-fill + bf16-split tensor GEMM + softmax/top2 + block-local scan =====
__global__ void __launch_bounds__(K1_THREADS)
k1_fused(const float* __restrict__ x, const float* __restrict__ W,
         const float* __restrict__ b, float* __restrict__ out, long long out_n)
{
    const int tid = threadIdx.x;
    const long long n4 = out_n >> 2;
    float4* o4 = (float4*)out;
    const float4 zz = make_float4(0.f, 0.f, 0.f, 0.f);

    // ---- dedicated store CTAs: drain the tail of the zero-fill, then exit ----
    if (blockIdx.x >= GEMM_BLOCKS) {
        long long idx = (long long)(blockIdx.x - GEMM_BLOCKS)*K1_THREADS + tid;
        for (long long zi = ZG + idx; zi < n4; zi += (long long)(K1_BLOCKS - GEMM_BLOCKS)*K1_THREADS)
            o4[zi] = zz;
        return;
    }

    __shared__ __align__(16) unsigned char sm[32768];
    const unsigned sb = (unsigned)__cvta_generic_to_shared(sm);
    const unsigned XH = 0, XL = 8192, WHs = 16384, WLs = 24576;

    const int T0   = blockIdx.x * MCTA;
    const int lane = tid & 31, w = tid >> 5;
    const int R0 = (w & 3) * 16;     // 16 token rows per warp
    const int C0 = (w >> 2) * 32;    // 32 experts per warp

    const long long zbase = (long long)blockIdx.x*K1_THREADS + tid;
    const long long zstr  = (long long)GEMM_BLOCKS*K1_THREADS;
    if (blockIdx.x == 0 && tid < (int)(out_n & 3LL)) out[n4*4 + tid] = 0.f;

    float acc[4][4];
#pragma unroll
    for (int i = 0; i < 4; ++i)
#pragma unroll
        for (int j = 0; j < 4; ++j) acc[i][j] = 0.f;

    // prefetch chunk 0
    float2 xv[8], wv[8];
#pragma unroll
    for (int i = 0; i < 8; ++i) {
        int idx = tid + K1_THREADS*i;
        int row = idx >> 5, p = idx & 31;
        xv[i] = *(const float2*)(x + (size_t)(T0 + row)*Dn + 2*p);
        wv[i] = *(const float2*)(W + (size_t)row*En + 2*p);
    }

    const int lm = lane >> 3;
    const int lr = lane & 7;
    const int arow = R0 + ((lm & 1) << 3) + lr;
    const int half = lm >> 1;

    for (int c = 0; c < NCHUNK; ++c) {
        __syncthreads();                      // tiles free
#pragma unroll
        for (int i = 0; i < 8; ++i) {
            int idx = tid + K1_THREADS*i;
            int row = idx >> 5, p = idx & 31;
            unsigned off = swz(row, p >> 2) + ((p & 3) << 2);
            __nv_bfloat162 h, l;
            h.x = __float2bfloat16(xv[i].x);
            h.y = __float2bfloat16(xv[i].y);
            l.x = __float2bfloat16(xv[i].x - __bfloat162float(h.x));
            l.y = __float2bfloat16(xv[i].y - __bfloat162float(h.y));
            *(__nv_bfloat162*)(sm + XH + off) = h;
            *(__nv_bfloat162*)(sm + XL + off) = l;
            h.x = __float2bfloat16(wv[i].x);
            h.y = __float2bfloat16(wv[i].y);
            l.x = __float2bfloat16(wv[i].x - __bfloat162float(h.x));
            l.y = __float2bfloat16(wv[i].y - __bfloat162float(h.y));
            *(__nv_bfloat162*)(sm + WHs + off) = h;
            *(__nv_bfloat162*)(sm + WLs + off) = l;
        }
        if (c + 1 < NCHUNK) {
            const int dc0 = (c + 1)*KC;
#pragma unroll
            for (int i = 0; i < 8; ++i) {
                int idx = tid + K1_THREADS*i;
                int row = idx >> 5, p = idx & 31;
                xv[i] = *(const float2*)(x + (size_t)(T0 + row)*Dn + dc0 + 2*p);
                wv[i] = *(const float2*)(W + (size_t)(dc0 + row)*En + 2*p);
            }
        }
        // interleaved zero-fill batch (first ZG float4 of output)
#pragma unroll
        for (int j = 0; j < ZPC; ++j) {
            long long zi = zbase + (long long)(c*ZPC + j)*zstr;
            if (zi < n4) o4[zi] = zz;
        }
        __syncthreads();                      // tiles ready

#pragma unroll
        for (int ks = 0; ks < 4; ++ks) {
            unsigned ah0,ah1,ah2,ah3, al0,al1,al2,al3;
            const unsigned aoff = swz(arow, 2*ks + half);
            LDSM4(ah0,ah1,ah2,ah3, sb + XH + aoff);
            LDSM4(al0,al1,al2,al3, sb + XL + aoff);
            const int krow = 16*ks + ((lm & 1) << 3) + lr;
            unsigned bh[8], bl[8];
            const unsigned boff0 = swz(krow, (C0 >> 3) + half);
            const unsigned boff1 = swz(krow, (C0 >> 3) + 2 + half);
            LDSM4T(bh[0],bh[1],bh[2],bh[3], sb + WHs + boff0);
            LDSM4T(bh[4],bh[5],bh[6],bh[7], sb + WHs + boff1);
            LDSM4T(bl[0],bl[1],bl[2],bl[3], sb + WLs + boff0);
            LDSM4T(bl[4],bl[5],bl[6],bl[7], sb + WLs + boff1);
#pragma unroll
            for (int nt = 0; nt < 4; ++nt) {
                HMMA(acc[nt], ah0,ah1,ah2,ah3, bh[2*nt], bh[2*nt+1]);
                HMMA(acc[nt], ah0,ah1,ah2,ah3, bl[2*nt], bl[2*nt+1]);
                HMMA(acc[nt], al0,al1,al2,al3, bh[2*nt], bh[2*nt+1]);
            }
        }
    }

    // ---- epilogue: accs -> smem logits -> softmax + top2 per token ----
    __syncthreads();                          // reuse sm
    float* lg = (float*)sm;                   // [64][64] at sm+0 (16 KB)
    unsigned char* se   = sm + 16384;         // [2][64] expert idx per slot
    unsigned char* lpos = sm + 16544;         // [2][64] local position
    int*           cntl = (int*)(sm + 16768); // [2][64] per-expert counts
    {
        const int g = lane >> 2, cc = (lane & 3)*2;
#pragma unroll
        for (int nt = 0; nt < 4; ++nt) {
            int e = C0 + nt*8 + cc;
            lg[(R0 + g)*En + e]     = acc[nt][0];
            lg[(R0 + g)*En + e + 1] = acc[nt][1];
            lg[(R0 + g + 8)*En + e]     = acc[nt][2];
            lg[(R0 + g + 8)*En + e + 1] = acc[nt][3];
        }
    }
    __syncthreads();

    {
        float2 bb = ((const float2*)b)[lane];
        const int e0 = 2*lane, e1 = 2*lane + 1;
        for (int r = w*8; r < w*8 + 8; ++r) {
            float2 v = *(float2*)&lg[r*En + 2*lane];
            float l0 = v.x + bb.x, l1 = v.y + bb.y;

            float m = fmaxf(l0, l1);
#pragma unroll
            for (int o = 16; o > 0; o >>= 1) m = fmaxf(m, __shfl_xor_sync(0xffffffffu, m, o));
            float p0 = expf(l0 - m), p1 = expf(l1 - m);
            float s = p0 + p1;
#pragma unroll
            for (int o = 16; o > 0; o >>= 1) s += __shfl_xor_sync(0xffffffffu, s, o);
            p0 = p0 / s;
            p1 = p1 / s;

            float wp; int we;
            if (p1 > p0) { wp = p1; we = e1; } else { wp = p0; we = e0; }
#pragma unroll
            for (int o = 16; o > 0; o >>= 1) {
                float op = __shfl_xor_sync(0xffffffffu, wp, o);
                int   oe = __shfl_xor_sync(0xffffffffu, we, o);
                if (op > wp || (op == wp && oe < we)) { wp = op; we = oe; }
            }
            float a0 = (e0 == we) ? -1.f : p0;
            float a1 = (e1 == we) ? -1.f : p1;
            float wp2; int we2;
            if (a1 > a0) { wp2 = a1; we2 = e1; } else { wp2 = a0; we2 = e0; }
#pragma unroll
            for (int o = 16; o > 0; o >>= 1) {
                float op = __shfl_xor_sync(0xffffffffu, wp2, o);
                int   oe = __shfl_xor_sync(0xffffffffu, we2, o);
                if (op > wp2 || (op == wp2 && oe < we2)) { wp2 = op; we2 = oe; }
            }
            if (lane == 0) {
                g_gate[T0 + r] = make_float2(wp, wp2);
                g_eidx[T0 + r] = make_int2(we, we2);
                se[r]      = (unsigned char)we;
                se[64 + r] = (unsigned char)we2;
            }
        }
    }
    __syncthreads();

    // ---- block-local rank scan for both slots (warps 0 and 1) ----
    if (tid < 128) cntl[tid] = 0;
    __syncthreads();
    if (w < 2) {
        const int slot = w;
#pragma unroll
        for (int it = 0; it < 2; ++it) {
            int t = it*32 + lane;
            int e = se[slot*64 + t];
            unsigned mask = __match_any_sync(0xffffffffu, e);
            int rank = __popc(mask & ((1u << lane) - 1u));
            int base = cntl[slot*64 + e];
            lpos[slot*64 + t] = (unsigned char)(base + rank);
            __syncwarp();
            if (rank == 0) cntl[slot*64 + e] = base + __popc(mask);
            __syncwarp();
        }
    }
    __syncthreads();

    const int gidx = T0 >> 11;              // group = T0 / Sn
    const int blk  = (T0 & (Sn - 1)) >> 6;  // 64-token block within group
    if (tid < 128) {
        int k = tid >> 6, e = tid & 63;
        g_cnt[((gidx*2 + k)*32 + blk)*En + e] = cntl[k*64 + e];
    }
    if (tid < 64)
        g_lpos[T0 + tid] = make_uchar2(lpos[tid], lpos[64 + tid]);
}

// ===== K3: 32 CTAs: smem-staged per-expert prefix over blocks + scatter =====
__global__ void __launch_bounds__(256)
k3_scatter(float* __restrict__ out, long long out_n,
           const int* __restrict__ capp, int has_mask)
{
    __shared__ int scnt[32*En];   // all 32 block-count vectors for this (g,k)
    __shared__ int base[8][En];

    const int gk = blockIdx.x >> 2, q = blockIdx.x & 3;
    const int g = gk >> 1, k = gk & 1;
    const int tid = threadIdx.x;
    int cap = 64;
    if (capp) { cap = capp[0]; if (cap > 64) cap = 64; }

    // stage counts via coalesced loads
#pragma unroll
    for (int i = 0; i < 8; ++i)
        scnt[tid + 256*i] = g_cnt[gk*32*En + tid + 256*i];
    __syncthreads();

    // per-expert prefix over blocks (fast LDS chain)
    if (tid < En) {
        int acc = 0;
        const int e = tid;
        const int bend = q*8 + 8;
        for (int bq = 0; bq < bend; ++bq) {
            if (bq >= q*8) base[bq - q*8][e] = acc;
            acc += scnt[bq*En + e];
        }
    }
    __syncthreads();

#pragma unroll
    for (int it = 0; it < 2; ++it) {
        int sl = q*512 + it*256 + tid;          // position within group
        int t  = g*Sn + sl;
        int2   ei = g_eidx[t];
        float2 gg = g_gate[t];
        uchar2 lp = g_lpos[t];
        int   e    = k ? ei.y : ei.x;
        float gate = k ? gg.y : gg.x;
        int   pos0 = base[(sl >> 6) & 7][e] + (int)(k ? lp.y : lp.x);
        if (pos0 + 1 < cap) {
            long long off = ((long long)t*En + e)*63 + pos0;
            if (off < out_n) out[off] = gate;
            if (has_mask) {
                long long moff = NCOMB + off;
                if (moff < out_n) out[moff] = (gate != 0.f) ? 1.f : 0.f;
            }
        }
    }
}

// ================= launch =================
extern "C" void kernel_launch(void* const* d_in, const int* in_sizes, int n_in,
                              void* d_out, int out_size)
{
    const float* x = (const float*)d_in[0];
    const float* W = (const float*)d_in[1];
    const float* b = (const float*)d_in[2];
    const int* capp = (n_in >= 4) ? (const int*)d_in[3] : nullptr;
    float* out = (float*)d_out;
    long long out_n = (long long)out_size;
    int has_mask = (out_n >= 2LL*NCOMB) ? 1 : 0;

    k1_fused<<<K1_BLOCKS, K1_THREADS>>>(x, W, b, out, out_n);
    k3_scatter<<<32, 256>>>(out, out_n, capp, has_mask);
}

// round 8
// speedup vs baseline: 1.9491x; 1.1269x over previous
#include <cuda_runtime.h>
#include <cuda_bf16.h>

// ---------------- problem constants ----------------
#define Gn 4
#define Sn 2048
#define Dn 2048
#define En 64
#define NTOK (Gn*Sn)                  // 8192 tokens
#define NCOMB ((long long)NTOK*En*63) // 33,030,144 combine elements
#define MCTA 64
#define KC 64
#define KWG 16                        // chunks per warpgroup (2 wgs x 16 x 64 = 2048)
#define K1_THREADS 512
#define GEMM_BLOCKS (NTOK/MCTA)       // 128
#define K1_BLOCKS 148                 // 128 GEMM + 20 dedicated store CTAs
#define ZPC 12                        // zero-fill float4/thread/iteration (GEMM CTAs)
#define ZG ((long long)GEMM_BLOCKS*K1_THREADS*ZPC*KWG)  // 12,582,912 float4
#define SMEM_K1 65536

// ---------------- device scratch ----------------
__device__ float2 g_gate[NTOK];
__device__ int2   g_eidx[NTOK];
__device__ uchar2 g_lpos[NTOK];                 // block-local 0-indexed pos per slot
__device__ int    g_cnt[8*32*En];               // [gk][blk][expert] counts

// swizzled byte offset inside a 64x64-bf16 tile (128B rows, XOR-16B swizzle)
__device__ __forceinline__ unsigned swz(int row, int chunk) {
    return (unsigned)(row*128 + ((chunk ^ (row & 7)) << 4));
}

#define LDSM4(R0_,R1_,R2_,R3_,ADDR) \
  asm volatile("ldmatrix.sync.aligned.m8n8.x4.shared.b16 {%0,%1,%2,%3}, [%4];" \
    : "=r"(R0_),"=r"(R1_),"=r"(R2_),"=r"(R3_) : "r"(ADDR))
#define LDSM4T(R0_,R1_,R2_,R3_,ADDR) \
  asm volatile("ldmatrix.sync.aligned.m8n8.x4.trans.shared.b16 {%0,%1,%2,%3}, [%4];" \
    : "=r"(R0_),"=r"(R1_),"=r"(R2_),"=r"(R3_) : "r"(ADDR))
#define HMMA(C_,A0,A1,A2,A3,B0,B1) \
  asm volatile("mma.sync.aligned.m16n8k16.row.col.f32.bf16.bf16.f32 " \
    "{%0,%1,%2,%3}, {%4,%5,%6,%7}, {%8,%9}, {%0,%1,%2,%3};" \
    : "+f"(C_[0]),"+f"(C_[1]),"+f"(C_[2]),"+f"(C_[3]) \
    : "r"(A0),"r"(A1),"r"(A2),"r"(A3),"r"(B0),"r"(B1))

// ===== K1: zero-fill + dual-warpgroup bf16-split tensor GEMM + softmax/top2 + scan =====
__global__ void __launch_bounds__(K1_THREADS)
k1_fused(const float* __restrict__ x, const float* __restrict__ W,
         const float* __restrict__ b, float* __restrict__ out, long long out_n)
{
    const int tid = threadIdx.x;
    const long long n4 = out_n >> 2;
    float4* o4 = (float4*)out;
    const float4 zz = make_float4(0.f, 0.f, 0.f, 0.f);

    // ---- dedicated store CTAs: drain the tail of the zero-fill, then exit ----
    if (blockIdx.x >= GEMM_BLOCKS) {
        long long idx = (long long)(blockIdx.x - GEMM_BLOCKS)*K1_THREADS + tid;
        for (long long zi = ZG + idx; zi < n4; zi += (long long)(K1_BLOCKS - GEMM_BLOCKS)*K1_THREADS)
            o4[zi] = zz;
        return;
    }

    extern __shared__ __align__(16) unsigned char smx[];   // 64 KB
    const int wg   = tid >> 8;          // warpgroup 0/1 (splits K)
    const int wtid = tid & 255;
    unsigned char* sm = smx + wg*32768;
    const unsigned sb = (unsigned)__cvta_generic_to_shared(sm);
    const unsigned XH = 0, XL = 8192, WHs = 16384, WLs = 24576;

    const int T0   = blockIdx.x * MCTA;
    const int lane = tid & 31;
    const int ww   = (tid >> 5) & 7;    // warp within warpgroup
    const int R0 = (ww & 3) * 16;       // 16 token rows per warp
    const int C0 = (ww >> 2) * 32;      // 32 experts per warp

    const long long zbase = (long long)blockIdx.x*K1_THREADS + tid;
    const long long zstr  = (long long)GEMM_BLOCKS*K1_THREADS;
    if (blockIdx.x == 0 && tid < (int)(out_n & 3LL)) out[n4*4 + tid] = 0.f;

    float acc[4][4];
#pragma unroll
    for (int i = 0; i < 4; ++i)
#pragma unroll
        for (int j = 0; j < 4; ++j) acc[i][j] = 0.f;

    const int dbase = wg * (KWG*KC);    // wg0: 0, wg1: 1024

    // prefetch chunk 0 of this warpgroup
    float2 xv[8], wv[8];
#pragma unroll
    for (int i = 0; i < 8; ++i) {
        int idx = wtid + 256*i;
        int row = idx >> 5, p = idx & 31;
        xv[i] = *(const float2*)(x + (size_t)(T0 + row)*Dn + dbase + 2*p);
        wv[i] = *(const float2*)(W + (size_t)(dbase + row)*En + 2*p);
    }

    const int lm = lane >> 3;
    const int lr = lane & 7;
    const int arow = R0 + ((lm & 1) << 3) + lr;
    const int half = lm >> 1;

    for (int c = 0; c < KWG; ++c) {
        __syncthreads();                      // tiles free
#pragma unroll
        for (int i = 0; i < 8; ++i) {
            int idx = wtid + 256*i;
            int row = idx >> 5, p = idx & 31;
            unsigned off = swz(row, p >> 2) + ((p & 3) << 2);
            __nv_bfloat162 h, l;
            h.x = __float2bfloat16(xv[i].x);
            h.y = __float2bfloat16(xv[i].y);
            l.x = __float2bfloat16(xv[i].x - __bfloat162float(h.x));
            l.y = __float2bfloat16(xv[i].y - __bfloat162float(h.y));
            *(__nv_bfloat162*)(sm + XH + off) = h;
            *(__nv_bfloat162*)(sm + XL + off) = l;
            h.x = __float2bfloat16(wv[i].x);
            h.y = __float2bfloat16(wv[i].y);
            l.x = __float2bfloat16(wv[i].x - __bfloat162float(h.x));
            l.y = __float2bfloat16(wv[i].y - __bfloat162float(h.y));
            *(__nv_bfloat162*)(sm + WHs + off) = h;
            *(__nv_bfloat162*)(sm + WLs + off) = l;
        }
        if (c + 1 < KWG) {
            const int dc0 = dbase + (c + 1)*KC;
#pragma unroll
            for (int i = 0; i < 8; ++i) {
                int idx = wtid + 256*i;
                int row = idx >> 5, p = idx & 31;
                xv[i] = *(const float2*)(x + (size_t)(T0 + row)*Dn + dc0 + 2*p);
                wv[i] = *(const float2*)(W + (size_t)(dc0 + row)*En + 2*p);
            }
        }
        // interleaved zero-fill batch (first ZG float4 of output)
#pragma unroll
        for (int j = 0; j < ZPC; ++j) {
            long long zi = zbase + (long long)(c*ZPC + j)*zstr;
            if (zi < n4) o4[zi] = zz;
        }
        __syncthreads();                      // tiles ready

#pragma unroll
        for (int ks = 0; ks < 4; ++ks) {
            unsigned ah0,ah1,ah2,ah3, al0,al1,al2,al3;
            const unsigned aoff = swz(arow, 2*ks + half);
            LDSM4(ah0,ah1,ah2,ah3, sb + XH + aoff);
            LDSM4(al0,al1,al2,al3, sb + XL + aoff);
            const int krow = 16*ks + ((lm & 1) << 3) + lr;
            unsigned bh[8], bl[8];
            const unsigned boff0 = swz(krow, (C0 >> 3) + half);
            const unsigned boff1 = swz(krow, (C0 >> 3) + 2 + half);
            LDSM4T(bh[0],bh[1],bh[2],bh[3], sb + WHs + boff0);
            LDSM4T(bh[4],bh[5],bh[6],bh[7], sb + WHs + boff1);
            LDSM4T(bl[0],bl[1],bl[2],bl[3], sb + WLs + boff0);
            LDSM4T(bl[4],bl[5],bl[6],bl[7], sb + WLs + boff1);
#pragma unroll
            for (int nt = 0; nt < 4; ++nt) {
                HMMA(acc[nt], ah0,ah1,ah2,ah3, bh[2*nt], bh[2*nt+1]);
                HMMA(acc[nt], ah0,ah1,ah2,ah3, bl[2*nt], bl[2*nt+1]);
                HMMA(acc[nt], al0,al1,al2,al3, bh[2*nt], bh[2*nt+1]);
            }
        }
    }

    // ---- epilogue: wg0 writes partial logits, wg1 accumulates ----
    __syncthreads();                          // all tile reads done; reuse smx
    float* lg = (float*)smx;                  // [64][64] (16 KB, wg0 region)
    unsigned char* se   = smx + 16384;        // [2][64] expert idx per slot
    unsigned char* lpos = smx + 16544;        // [2][64] local position
    int*           cntl = (int*)(smx + 16768);// [2][64] per-expert counts
    {
        const int g = lane >> 2, cc = (lane & 3)*2;
        if (wg == 0) {
#pragma unroll
            for (int nt = 0; nt < 4; ++nt) {
                int e = C0 + nt*8 + cc;
                lg[(R0 + g)*En + e]         = acc[nt][0];
                lg[(R0 + g)*En + e + 1]     = acc[nt][1];
                lg[(R0 + g + 8)*En + e]     = acc[nt][2];
                lg[(R0 + g + 8)*En + e + 1] = acc[nt][3];
            }
        }
        __syncthreads();
        if (wg == 1) {
#pragma unroll
            for (int nt = 0; nt < 4; ++nt) {
                int e = C0 + nt*8 + cc;
                lg[(R0 + g)*En + e]         += acc[nt][0];
                lg[(R0 + g)*En + e + 1]     += acc[nt][1];
                lg[(R0 + g + 8)*En + e]     += acc[nt][2];
                lg[(R0 + g + 8)*En + e + 1] += acc[nt][3];
            }
        }
    }
    __syncthreads();

    // ---- softmax + top2: 16 warps x 4 rows ----
    {
        float2 bb = ((const float2*)b)[lane];
        const int e0 = 2*lane, e1 = 2*lane + 1;
        const int wglob = tid >> 5;           // 0..15
        for (int r = wglob*4; r < wglob*4 + 4; ++r) {
            float2 v = *(float2*)&lg[r*En + 2*lane];
            float l0 = v.x + bb.x, l1 = v.y + bb.y;

            float m = fmaxf(l0, l1);
#pragma unroll
            for (int o = 16; o > 0; o >>= 1) m = fmaxf(m, __shfl_xor_sync(0xffffffffu, m, o));
            float p0 = expf(l0 - m), p1 = expf(l1 - m);
            float s = p0 + p1;
#pragma unroll
            for (int o = 16; o > 0; o >>= 1) s += __shfl_xor_sync(0xffffffffu, s, o);
            p0 = p0 / s;
            p1 = p1 / s;

            float wp; int we;
            if (p1 > p0) { wp = p1; we = e1; } else { wp = p0; we = e0; }
#pragma unroll
            for (int o = 16; o > 0; o >>= 1) {
                float op = __shfl_xor_sync(0xffffffffu, wp, o);
                int   oe = __shfl_xor_sync(0xffffffffu, we, o);
                if (op > wp || (op == wp && oe < we)) { wp = op; we = oe; }
            }
            float a0 = (e0 == we) ? -1.f : p0;
            float a1 = (e1 == we) ? -1.f : p1;
            float wp2; int we2;
            if (a1 > a0) { wp2 = a1; we2 = e1; } else { wp2 = a0; we2 = e0; }
#pragma unroll
            for (int o = 16; o > 0; o >>= 1) {
                float op = __shfl_xor_sync(0xffffffffu, wp2, o);
                int   oe = __shfl_xor_sync(0xffffffffu, we2, o);
                if (op > wp2 || (op == wp2 && oe < we2)) { wp2 = op; we2 = oe; }
            }
            if (lane == 0) {
                g_gate[T0 + r] = make_float2(wp, wp2);
                g_eidx[T0 + r] = make_int2(we, we2);
                se[r]      = (unsigned char)we;
                se[64 + r] = (unsigned char)we2;
            }
        }
    }
    __syncthreads();

    // ---- block-local rank scan for both slots (warps 0 and 1) ----
    if (tid < 128) cntl[tid] = 0;
    __syncthreads();
    if ((tid >> 5) < 2) {
        const int slot = tid >> 5;
#pragma unroll
        for (int it = 0; it < 2; ++it) {
            int t = it*32 + lane;
            int e = se[slot*64 + t];
            unsigned mask = __match_any_sync(0xffffffffu, e);
            int rank = __popc(mask & ((1u << lane) - 1u));
            int base = cntl[slot*64 + e];
            lpos[slot*64 + t] = (unsigned char)(base + rank);
            __syncwarp();
            if (rank == 0) cntl[slot*64 + e] = base + __popc(mask);
            __syncwarp();
        }
    }
    __syncthreads();

    const int gidx = T0 >> 11;              // group = T0 / Sn
    const int blk  = (T0 & (Sn - 1)) >> 6;  // 64-token block within group
    if (tid < 128) {
        int k = tid >> 6, e = tid & 63;
        g_cnt[((gidx*2 + k)*32 + blk)*En + e] = cntl[k*64 + e];
    }
    if (tid < 64)
        g_lpos[T0 + tid] = make_uchar2(lpos[tid], lpos[64 + tid]);
}

// ===== K3: 64 CTAs: smem-staged per-expert prefix over blocks + scatter =====
__global__ void __launch_bounds__(256)
k3_scatter(float* __restrict__ out, long long out_n,
           const int* __restrict__ capp, int has_mask)
{
    __shared__ int scnt[32*En];   // all 32 block-count vectors for this (g,k)
    __shared__ int base[4][En];

    const int gk = blockIdx.x >> 3, q = blockIdx.x & 7;
    const int g = gk >> 1, k = gk & 1;
    const int tid = threadIdx.x;
    int cap = 64;
    if (capp) { cap = capp[0]; if (cap > 64) cap = 64; }

    // stage counts via coalesced loads
#pragma unroll
    for (int i = 0; i < 8; ++i)
        scnt[tid + 256*i] = g_cnt[gk*32*En + tid + 256*i];
    __syncthreads();

    // per-expert prefix over blocks (LDS chain)
    if (tid < En) {
        int acc = 0;
        const int e = tid;
        const int bend = q*4 + 4;
        for (int bq = 0; bq < bend; ++bq) {
            if (bq >= q*4) base[bq - q*4][e] = acc;
            acc += scnt[bq*En + e];
        }
    }
    __syncthreads();

    int sl = q*256 + tid;          // position within group
    int t  = g*Sn + sl;
    int2   ei = g_eidx[t];
    float2 gg = g_gate[t];
    uchar2 lp = g_lpos[t];
    int   e    = k ? ei.y : ei.x;
    float gate = k ? gg.y : gg.x;
    int   pos0 = base[(sl >> 6) & 3][e] + (int)(k ? lp.y : lp.x);
    if (pos0 + 1 < cap) {
        long long off = ((long long)t*En + e)*63 + pos0;
        if (off < out_n) out[off] = gate;
        if (has_mask) {
            long long moff = NCOMB + off;
            if (moff < out_n) out[moff] = (gate != 0.f) ? 1.f : 0.f;
        }
    }
}

// ================= launch =================
extern "C" void kernel_launch(void* const* d_in, const int* in_sizes, int n_in,
                              void* d_out, int out_size)
{
    const float* x = (const float*)d_in[0];
    const float* W = (const float*)d_in[1];
    const float* b = (const float*)d_in[2];
    const int* capp = (n_in >= 4) ? (const int*)d_in[3] : nullptr;
    float* out = (float*)d_out;
    long long out_n = (long long)out_size;
    int has_mask = (out_n >= 2LL*NCOMB) ? 1 : 0;

    cudaFuncSetAttribute(k1_fused, cudaFuncAttributeMaxDynamicSharedMemorySize, SMEM_K1);
    k1_fused<<<K1_BLOCKS, K1_THREADS, SMEM_K1>>>(x, W, b, out, out_n);
    k3_scatter<<<64, 256>>>(out, out_n, capp, has_mask);
}